// round 6
// baseline (speedup 1.0000x reference)
#include <cuda_runtime.h>
#include <cuda_fp16.h>
#include <cstdint>

// RandomWalkPE: diag(T^k), k=1..8, T = D^-1 A (A = symmetrized multigraph adjacency),
// then [N,8] @ W_pe[8,16] + b_pe.
//
// Identities (A symmetric => T^b[j,i] = deg_i * T^b[i,j] / deg_j):
//   d2 = T2[i,i]                                        (fp32, k_t2)
//   d3 = T3[i,i]                                        (fp32, k_t3)
//   d4 = deg_i * sum_j w_ij * T3[i,j] * invdeg[j]       (sparse, fp32 T3 regs, k_t3)
//   d5 = deg_i * sum_c T2[i,c]*T3[i,c]*invdeg[c]        (fp32 T3 regs, k_t3)
//   d6 = deg_i * sum_c T3[i,c]^2 * invdeg[c]            (fp32 T3 regs, k_t3)
//   d7 = deg_i * sum_c T3[i,c]*T4[i,c]*invdeg[c]        (k_final)
//   d8 = deg_i * sum_c T4[i,c]^2 * invdeg[c]            (k_final)
// T2, T3 stored fp16 (fp32 accumulation); T4 rows live only in registers.

#define NN   4096
#define NE   65536
#define CAP  128
#define DPE  16

__device__ int   g_hcol[NN * CAP];     // open-addressing hash: column (or -1)
__device__ float g_hw  [NN * CAP];     // hash: multiplicity count
__device__ __align__(16) int2 g_cw[NN * CAP];   // packed CSR: {col, bits(weight)}
__device__ int   g_nnz [NN];
__device__ float g_deg [NN];
__device__ __align__(16) float g_invdeg[NN];
__device__ float g_wii[NN];
__device__ float g_d2[NN], g_d3[NN], g_d4[NN], g_d5[NN], g_d6[NN];
__device__ __align__(16) __half g_T2h[(size_t)NN * NN];          // 32 MB
__device__ __align__(16) __half g_T3h[(size_t)NN * NN];          // 32 MB

// ---------------- K1: init hash tables ----------------
__global__ void k_hinit() {
    int idx = blockIdx.x * blockDim.x + threadIdx.x;     // NN*CAP/4 threads
    reinterpret_cast<int4*>(g_hcol)[idx]  = make_int4(-1, -1, -1, -1);
    reinterpret_cast<float4*>(g_hw)[idx]  = make_float4(0.f, 0.f, 0.f, 0.f);
}

// ---------------- K2: hash-insert symmetrized edges ----------------
__device__ __forceinline__ void hins(int r, int c) {
    int base = r * CAP;
    unsigned slot = ((unsigned)c * 2654435761u) >> 25;   // 7-bit hash
    for (;;) {
        int prev = atomicCAS(&g_hcol[base + slot], -1, c);
        if (prev == -1 || prev == c) { atomicAdd(&g_hw[base + slot], 1.0f); return; }
        slot = (slot + 1) & (CAP - 1);
    }
}

__global__ void k_insert(const int* __restrict__ ei) {
    int e = blockIdx.x * blockDim.x + threadIdx.x;
    if (e < NE) {
        int r = ei[e];
        int c = ei[NE + e];
        hins(r, c);
        hins(c, r);
    }
}

// ---------------- K3: compact + normalize (1 block of 128 per row) ----------------
__global__ void __launch_bounds__(128) k_compact() {
    int i = blockIdx.x, t = threadIdx.x;
    int   col = g_hcol[i * CAP + t];
    float w   = g_hw  [i * CAP + t];
    float v = (col >= 0) ? w : 0.f;

    for (int off = 16; off > 0; off >>= 1) v += __shfl_down_sync(0xffffffffu, v, off);
    __shared__ float red[4];
    if ((t & 31) == 0) red[t >> 5] = v;
    __syncthreads();
    __shared__ float s_inv, s_wii;
    __shared__ int   s_cnt;
    if (t == 0) {
        float d = fmaxf(red[0] + red[1] + red[2] + red[3], 1.0f);
        g_deg[i] = d;
        s_inv = 1.0f / d;
        g_invdeg[i] = s_inv;
        s_cnt = 0; s_wii = 0.f;
    }
    __syncthreads();
    float inv = s_inv;
    if (col >= 0) {
        if (col == i) s_wii = w * inv;
        int p = atomicAdd(&s_cnt, 1);
        g_cw[i * CAP + p] = make_int2(col, __float_as_int(w * inv));
    }
    __syncthreads();
    if (t == 0) { g_nnz[i] = s_cnt; g_wii[i] = s_wii; }
}

// ---------------- pack/unpack helpers ----------------
__device__ __forceinline__ uint4 pack8(const float* a) {
    uint4 u;
    __half2 h0 = __floats2half2_rn(a[0], a[1]);
    __half2 h1 = __floats2half2_rn(a[2], a[3]);
    __half2 h2 = __floats2half2_rn(a[4], a[5]);
    __half2 h3 = __floats2half2_rn(a[6], a[7]);
    u.x = *reinterpret_cast<unsigned int*>(&h0);
    u.y = *reinterpret_cast<unsigned int*>(&h1);
    u.z = *reinterpret_cast<unsigned int*>(&h2);
    u.w = *reinterpret_cast<unsigned int*>(&h3);
    return u;
}

__device__ __forceinline__ void unpack_fma(uint4 v, float w, float* a) {
    __half2 h0 = *reinterpret_cast<__half2*>(&v.x);
    __half2 h1 = *reinterpret_cast<__half2*>(&v.y);
    __half2 h2 = *reinterpret_cast<__half2*>(&v.z);
    __half2 h3 = *reinterpret_cast<__half2*>(&v.w);
    float2 f0 = __half22float2(h0), f1 = __half22float2(h1);
    float2 f2 = __half22float2(h2), f3 = __half22float2(h3);
    a[0] = fmaf(w, f0.x, a[0]); a[1] = fmaf(w, f0.y, a[1]);
    a[2] = fmaf(w, f1.x, a[2]); a[3] = fmaf(w, f1.y, a[3]);
    a[4] = fmaf(w, f2.x, a[4]); a[5] = fmaf(w, f2.y, a[5]);
    a[6] = fmaf(w, f3.x, a[6]); a[7] = fmaf(w, f3.y, a[7]);
}

__device__ __forceinline__ void unpack8(uint4 v, float* f) {
    __half2 h0 = *reinterpret_cast<__half2*>(&v.x);
    __half2 h1 = *reinterpret_cast<__half2*>(&v.y);
    __half2 h2 = *reinterpret_cast<__half2*>(&v.z);
    __half2 h3 = *reinterpret_cast<__half2*>(&v.w);
    float2 f0 = __half22float2(h0), f1 = __half22float2(h1);
    float2 f2 = __half22float2(h2), f3 = __half22float2(h3);
    f[0] = f0.x; f[1] = f0.y; f[2] = f1.x; f[3] = f1.y;
    f[4] = f2.x; f[5] = f2.y; f[6] = f3.x; f[7] = f3.y;
}

__device__ __forceinline__ float warp_red(float v) {
    for (int off = 16; off > 0; off >>= 1) v += __shfl_down_sync(0xffffffffu, v, off);
    return v;
}

// gather: a[0..7] += sum_p sw[p] * M[scol[p], 8t..8t+7], software-pipelined
__device__ __forceinline__ void gather_rows(const __half* __restrict__ M,
                                            const int* scol, const float* sw,
                                            int nn, int t, float* a) {
    if (nn <= 0) return;
    uint4 v = reinterpret_cast<const uint4*>(M + (size_t)scol[0] * NN)[t];
    #pragma unroll 2
    for (int p = 1; p < nn; p++) {
        uint4 vn = reinterpret_cast<const uint4*>(M + (size_t)scol[p] * NN)[t];
        unpack_fma(v, sw[p - 1], a);
        v = vn;
    }
    unpack_fma(v, sw[nn - 1], a);
}

// ---------------- K4: T2 = T*T, warp-per-neighbor scatter, fp16 store ------------
__global__ void __launch_bounds__(512) k_t2() {
    int i = blockIdx.x, t = threadIdx.x, wid = t >> 5, lane = t & 31;
    __shared__ float acc[NN];            // 16 KB
    __shared__ int   scol[CAP];
    __shared__ float sw[CAP];
    float4* a4 = reinterpret_cast<float4*>(acc);
    float4 z = make_float4(0.f, 0.f, 0.f, 0.f);
    a4[t] = z; a4[t + 512] = z;
    int nn = g_nnz[i];
    if (t < nn) {
        int2 cw = g_cw[i * CAP + t];
        scol[t] = cw.x;
        sw[t]   = __int_as_float(cw.y);
    }
    __syncthreads();
    for (int p = wid; p < nn; p += 16) {         // 16 warps over neighbors
        int   j   = scol[p];
        float wij = sw[p];
        int   nj  = g_nnz[j];
        const int2* jcw = g_cw + j * CAP;
        for (int q = lane; q < nj; q += 32) {
            int2 cw = __ldg(jcw + q);
            atomicAdd(&acc[cw.x], wij * __int_as_float(cw.y));
        }
    }
    __syncthreads();
    reinterpret_cast<uint4*>(g_T2h + (size_t)i * NN)[t] = pack8(&acc[8 * t]);
    if (t == 0) g_d2[i] = acc[i];                // exact fp32 diagonal
}

// ------- K5: T3 = T*T2 (fp16 gather, fp32 acc); d3, d4, d5, d6; fp16 store -------
__global__ void __launch_bounds__(512) k_t3() {
    int i = blockIdx.x, t = threadIdx.x;
    __shared__ int   scol[CAP];
    __shared__ float sw[CAP];
    int nn = g_nnz[i];
    if (t < nn) {
        int2 cw = g_cw[i * CAP + t];
        scol[t] = cw.x;
        sw[t]   = __int_as_float(cw.y);
    }
    __syncthreads();
    float a[8] = {0, 0, 0, 0, 0, 0, 0, 0};       // T3[i, 8t..8t+7] fp32
    gather_rows(g_T2h, scol, sw, nn, t, a);
    reinterpret_cast<uint4*>(g_T3h + (size_t)i * NN)[t] = pack8(a);

    int base = t * 8;
    if ((i >> 3) == t) g_d3[i] = a[i & 7];       // fp32 diagonal

    // d4 = deg_i * sum_j(sparse) w_ij * T3[i,j] * invdeg[j]  (each thread owns 8 cols)
    float s4 = 0.f;
    for (int p = 0; p < nn; p++) {
        int j = scol[p];
        if ((j >> 3) == t) s4 += sw[p] * a[j & 7] * __ldg(&g_invdeg[j]);
    }

    // d5 = (2,3), d6 = (3,3)
    float u2[8];
    unpack8(reinterpret_cast<const uint4*>(g_T2h + (size_t)i * NN)[t], u2);
    float4 iv0 = *reinterpret_cast<const float4*>(g_invdeg + base);
    float4 iv1 = *reinterpret_cast<const float4*>(g_invdeg + base + 4);
    float iv[8] = {iv0.x, iv0.y, iv0.z, iv0.w, iv1.x, iv1.y, iv1.z, iv1.w};
    float s5 = 0.f, s6 = 0.f;
    #pragma unroll
    for (int k = 0; k < 8; k++) {
        float wa = a[k] * iv[k];
        s5 = fmaf(u2[k], wa, s5);
        s6 = fmaf(a[k],  wa, s6);
    }
    __shared__ float red[3][16];
    s4 = warp_red(s4); s5 = warp_red(s5); s6 = warp_red(s6);
    int wid = t >> 5, lane = t & 31;
    if (lane == 0) { red[0][wid] = s4; red[1][wid] = s5; red[2][wid] = s6; }
    __syncthreads();
    if (t < 3) {
        float x = 0.f;
        for (int q = 0; q < 16; q++) x += red[t][q];
        float d = g_deg[i] * x;
        if (t == 0) g_d4[i] = d; else if (t == 1) g_d5[i] = d; else g_d6[i] = d;
    }
}

// ------- K6: T4 row (fp16 gather, fp32 acc) + d7, d8 + PE projection -------
__global__ void __launch_bounds__(512) k_final(const float* __restrict__ W,
                                               const float* __restrict__ b,
                                               float* __restrict__ out) {
    int i = blockIdx.x, t = threadIdx.x;
    __shared__ int   scol[CAP];
    __shared__ float sw[CAP];
    int nn = g_nnz[i];
    if (t < nn) {
        int2 cw = g_cw[i * CAP + t];
        scol[t] = cw.x;
        sw[t]   = __int_as_float(cw.y);
    }
    __syncthreads();
    float a[8] = {0, 0, 0, 0, 0, 0, 0, 0};       // T4[i, 8t..8t+7] fp32
    gather_rows(g_T3h, scol, sw, nn, t, a);

    int base = t * 8;
    float u3[8];                                  // T3 row i (fp16)
    unpack8(reinterpret_cast<const uint4*>(g_T3h + (size_t)i * NN)[t], u3);
    float4 iv0 = *reinterpret_cast<const float4*>(g_invdeg + base);
    float4 iv1 = *reinterpret_cast<const float4*>(g_invdeg + base + 4);
    float iv[8] = {iv0.x, iv0.y, iv0.z, iv0.w, iv1.x, iv1.y, iv1.z, iv1.w};
    float s7 = 0.f, s8 = 0.f;
    #pragma unroll
    for (int k = 0; k < 8; k++) {
        float wa = a[k] * iv[k];
        s7 = fmaf(u3[k], wa, s7);
        s8 = fmaf(a[k],  wa, s8);
    }
    __shared__ float red[2][16];
    s7 = warp_red(s7); s8 = warp_red(s8);
    int wid = t >> 5, lane = t & 31;
    if (lane == 0) { red[0][wid] = s7; red[1][wid] = s8; }
    __syncthreads();
    __shared__ float S[2];
    if (t < 2) {
        float x = 0.f;
        for (int q = 0; q < 16; q++) x += red[t][q];
        S[t] = x;
    }
    __syncthreads();

    if (t < DPE) {
        float deg = g_deg[i];
        float d1 = g_wii[i];
        float d2 = g_d2[i], d3 = g_d3[i], d4 = g_d4[i];
        float d5 = g_d5[i], d6 = g_d6[i];
        float d7 = deg * S[0], d8 = deg * S[1];
        float o = b[t];
        o = fmaf(d1, W[0 * DPE + t], o);
        o = fmaf(d2, W[1 * DPE + t], o);
        o = fmaf(d3, W[2 * DPE + t], o);
        o = fmaf(d4, W[3 * DPE + t], o);
        o = fmaf(d5, W[4 * DPE + t], o);
        o = fmaf(d6, W[5 * DPE + t], o);
        o = fmaf(d7, W[6 * DPE + t], o);
        o = fmaf(d8, W[7 * DPE + t], o);
        out[i * DPE + t] = o;
    }
}

extern "C" void kernel_launch(void* const* d_in, const int* in_sizes, int n_in,
                              void* d_out, int out_size) {
    const int*   edge = nullptr;
    const float* W    = nullptr;
    const float* bias = nullptr;
    for (int k = 0; k < n_in; k++) {
        if (in_sizes[k] == 2 * NE)       edge = (const int*)d_in[k];
        else if (in_sizes[k] == 8 * DPE) W    = (const float*)d_in[k];
        else if (in_sizes[k] == DPE)     bias = (const float*)d_in[k];
    }
    float* out = (float*)d_out;

    k_hinit  <<<(NN * CAP / 4) / 256, 256>>>();
    k_insert <<<(NE + 255) / 256, 256>>>(edge);
    k_compact<<<NN, 128>>>();
    k_t2     <<<NN, 512>>>();
    k_t3     <<<NN, 512>>>();
    k_final  <<<NN, 512>>>(W, bias, out);
}

// round 7
// speedup vs baseline: 1.2596x; 1.2596x over previous
#include <cuda_runtime.h>
#include <cuda_fp16.h>
#include <cstdint>

// RandomWalkPE: diag(T^k), k=1..8, T = D^-1 A (A = symmetrized multigraph adjacency),
// then [N,8] @ W_pe[8,16] + b_pe.
//
// All storage fp8 e4m3 scaled x256; gathers accumulate in half2 (HFMA2).
// Diagonal extraction (S = T^2, symmetric-walk identity M^k[j,i] = deg_i M^k[i,j] invdeg_j):
//   d1 = T[i,i]                                   (CSR, exact)
//   d2 = S[i,i]                                   (fp32 smem acc in k_t2, exact)
//   d3 = deg_i sum_{c in nbr} w_ic S[i,c] invdeg_c        (fp32, k_t2, exact)
//   d4 = deg_i sum_c S[i,c]^2 invdeg_c                    (fp32, k_t2, exact)
//   d5 = deg_i sum_{c in nbr} w_ic T4[i,c] invdeg_c       (k_final, (1,4) split)
//   d6 = deg_i sum_c T3[i,c]^2 invdeg_c                   (k_t3,  (3,3) split)
//   d7 = deg_i sum_c T3[i,c] T4[i,c] invdeg_c             (k_final, (3,4) split)
//   d8 = deg_i sum_c T4[i,c]^2 invdeg_c                   (k_final, (4,4) split)

#define NN   4096
#define NE   65536
#define CAP  128
#define DPE  16
#define FSCALE 256.0f

__device__ int   g_hcol[NN * CAP];     // open-addressing hash: column (or -1)
__device__ float g_hw  [NN * CAP];     // hash: multiplicity count
__device__ __align__(16) int2 g_cw[NN * CAP];   // packed CSR: {col, bits(weight)}
__device__ int   g_nnz [NN];
__device__ float g_deg [NN];
__device__ __align__(16) float g_invdeg[NN];
__device__ float g_wii[NN];
__device__ float g_d2[NN], g_d3[NN], g_d4[NN], g_d6[NN];
__device__ __align__(16) unsigned char g_T2q[(size_t)NN * NN];   // 16 MB, e4m3 x256
__device__ __align__(16) unsigned char g_T3q[(size_t)NN * NN];   // 16 MB, e4m3 x256

// ---------------- K1: init hash tables ----------------
__global__ void k_hinit() {
    int idx = blockIdx.x * blockDim.x + threadIdx.x;     // NN*CAP/4 threads
    reinterpret_cast<int4*>(g_hcol)[idx]  = make_int4(-1, -1, -1, -1);
    reinterpret_cast<float4*>(g_hw)[idx]  = make_float4(0.f, 0.f, 0.f, 0.f);
}

// ---------------- K2: hash-insert symmetrized edges ----------------
__device__ __forceinline__ void hins(int r, int c) {
    int base = r * CAP;
    unsigned slot = ((unsigned)c * 2654435761u) >> 25;   // 7-bit hash
    for (;;) {
        int prev = atomicCAS(&g_hcol[base + slot], -1, c);
        if (prev == -1 || prev == c) { atomicAdd(&g_hw[base + slot], 1.0f); return; }
        slot = (slot + 1) & (CAP - 1);
    }
}

__global__ void k_insert(const int* __restrict__ ei) {
    int e = blockIdx.x * blockDim.x + threadIdx.x;
    if (e < NE) {
        int r = ei[e];
        int c = ei[NE + e];
        hins(r, c);
        hins(c, r);
    }
}

// ---------------- K3: compact + normalize (1 block of 128 per row) ----------------
__global__ void __launch_bounds__(128) k_compact() {
    int i = blockIdx.x, t = threadIdx.x;
    int   col = g_hcol[i * CAP + t];
    float w   = g_hw  [i * CAP + t];
    float v = (col >= 0) ? w : 0.f;

    for (int off = 16; off > 0; off >>= 1) v += __shfl_down_sync(0xffffffffu, v, off);
    __shared__ float red[4];
    if ((t & 31) == 0) red[t >> 5] = v;
    __syncthreads();
    __shared__ float s_inv, s_wii;
    __shared__ int   s_cnt;
    if (t == 0) {
        float d = fmaxf(red[0] + red[1] + red[2] + red[3], 1.0f);
        g_deg[i] = d;
        s_inv = 1.0f / d;
        g_invdeg[i] = s_inv;
        s_cnt = 0; s_wii = 0.f;
    }
    __syncthreads();
    float inv = s_inv;
    if (col >= 0) {
        if (col == i) s_wii = w * inv;
        int p = atomicAdd(&s_cnt, 1);
        g_cw[i * CAP + p] = make_int2(col, __float_as_int(w * inv));
    }
    __syncthreads();
    if (t == 0) { g_nnz[i] = s_cnt; g_wii[i] = s_wii; }
}

// ---------------- helpers ----------------
__device__ __forceinline__ uint2 pack8_fp8_f32(const float* a) {
    unsigned short s0, s1, s2, s3;
    asm("cvt.rn.satfinite.e4m3x2.f32 %0, %1, %2;" : "=h"(s0) : "f"(a[1] * FSCALE), "f"(a[0] * FSCALE));
    asm("cvt.rn.satfinite.e4m3x2.f32 %0, %1, %2;" : "=h"(s1) : "f"(a[3] * FSCALE), "f"(a[2] * FSCALE));
    asm("cvt.rn.satfinite.e4m3x2.f32 %0, %1, %2;" : "=h"(s2) : "f"(a[5] * FSCALE), "f"(a[4] * FSCALE));
    asm("cvt.rn.satfinite.e4m3x2.f32 %0, %1, %2;" : "=h"(s3) : "f"(a[7] * FSCALE), "f"(a[6] * FSCALE));
    uint2 u;
    u.x = (unsigned)s0 | ((unsigned)s1 << 16);
    u.y = (unsigned)s2 | ((unsigned)s3 << 16);
    return u;
}

__device__ __forceinline__ unsigned short h2_to_fp8(__half2 h) {
    unsigned hb = *reinterpret_cast<unsigned*>(&h);
    unsigned short s;
    asm("cvt.rn.satfinite.e4m3x2.f16x2 %0, %1;" : "=h"(s) : "r"(hb));
    return s;
}

__device__ __forceinline__ __half2 fp8_to_h2(unsigned short p) {
    unsigned r;
    asm("cvt.rn.f16x2.e4m3x2 %0, %1;" : "=r"(r) : "h"(p));
    return *reinterpret_cast<__half2*>(&r);
}

__device__ __forceinline__ float warp_red(float v) {
    for (int off = 16; off > 0; off >>= 1) v += __shfl_down_sync(0xffffffffu, v, off);
    return v;
}

// ---------------- K4: S = T*T scatter (fp32 smem), fp8 store, d2/d3/d4 exact --------
__global__ void __launch_bounds__(512) k_t2() {
    int i = blockIdx.x, t = threadIdx.x, wid = t >> 5, lane = t & 31;
    __shared__ float acc[NN];            // 16 KB
    __shared__ int   scol[CAP];
    __shared__ float sw[CAP];
    float4* a4 = reinterpret_cast<float4*>(acc);
    float4 z = make_float4(0.f, 0.f, 0.f, 0.f);
    a4[t] = z; a4[t + 512] = z;
    int nn = g_nnz[i];
    if (t < nn) {
        int2 cw = g_cw[i * CAP + t];
        scol[t] = cw.x;
        sw[t]   = __int_as_float(cw.y);
    }
    __syncthreads();
    for (int p = wid; p < nn; p += 16) {         // 16 warps over neighbors
        int   j   = scol[p];
        float wij = sw[p];
        int   nj  = g_nnz[j];
        const int2* jcw = g_cw + j * CAP;
        for (int q = lane; q < nj; q += 32) {
            int2 cw = __ldg(jcw + q);
            atomicAdd(&acc[cw.x], wij * __int_as_float(cw.y));
        }
    }
    __syncthreads();
    // fp8 store of S row
    reinterpret_cast<uint2*>(g_T2q + (size_t)i * NN)[t] = pack8_fp8_f32(&acc[8 * t]);

    // d4 = deg * sum_c S[i,c]^2 * invdeg[c]   (exact fp32)
    int base = 8 * t;
    float4 iv0 = *reinterpret_cast<const float4*>(g_invdeg + base);
    float4 iv1 = *reinterpret_cast<const float4*>(g_invdeg + base + 4);
    float iv[8] = {iv0.x, iv0.y, iv0.z, iv0.w, iv1.x, iv1.y, iv1.z, iv1.w};
    float s4 = 0.f;
    #pragma unroll
    for (int k = 0; k < 8; k++) s4 = fmaf(acc[base + k] * iv[k], acc[base + k], s4);

    // d3 = deg * sum_{p} w_ip * S[i, col_p] * invdeg[col_p]   (exact fp32)
    float s3 = 0.f;
    if (t < nn) {
        int j = scol[t];
        s3 = sw[t] * acc[j] * __ldg(&g_invdeg[j]);
    }

    __shared__ float red[2][16];
    s3 = warp_red(s3); s4 = warp_red(s4);
    if (lane == 0) { red[0][wid] = s3; red[1][wid] = s4; }
    __syncthreads();
    if (t < 2) {
        float x = 0.f;
        for (int q = 0; q < 16; q++) x += red[t][q];
        float d = g_deg[i] * x;
        if (t == 0) g_d3[i] = d; else g_d4[i] = d;
    }
    if (t == 256) g_d2[i] = acc[i];
}

// ------- K5: T3 = T*S (fp8 gather, half2 acc), fp8 store, d6 -------
__global__ void __launch_bounds__(512) k_t3() {
    int i = blockIdx.x, t = threadIdx.x;
    __shared__ int   scol[CAP];
    __shared__ float sw[CAP];
    int nn = g_nnz[i];
    if (t < nn) {
        int2 cw = g_cw[i * CAP + t];
        scol[t] = cw.x;
        sw[t]   = __int_as_float(cw.y);
    }
    __syncthreads();
    __half2 c0 = __half2half2(__ushort_as_half(0));
    __half2 c1 = c0, c2 = c0, c3 = c0;           // 256*T3[i, 8t..8t+7]
    for (int p = 0; p < nn; p++) {
        int j = scol[p];
        __half2 w2 = __float2half2_rn(sw[p]);
        uint2 v = __ldg(reinterpret_cast<const uint2*>(g_T2q + (size_t)j * NN) + t);
        c0 = __hfma2(fp8_to_h2((unsigned short)(v.x & 0xffffu)), w2, c0);
        c1 = __hfma2(fp8_to_h2((unsigned short)(v.x >> 16)),     w2, c1);
        c2 = __hfma2(fp8_to_h2((unsigned short)(v.y & 0xffffu)), w2, c2);
        c3 = __hfma2(fp8_to_h2((unsigned short)(v.y >> 16)),     w2, c3);
    }
    // store fp8 (values already x256 scaled)
    uint2 u;
    u.x = (unsigned)h2_to_fp8(c0) | ((unsigned)h2_to_fp8(c1) << 16);
    u.y = (unsigned)h2_to_fp8(c2) | ((unsigned)h2_to_fp8(c3) << 16);
    reinterpret_cast<uint2*>(g_T3q + (size_t)i * NN)[t] = u;

    // d6 = deg/FSCALE^2 * sum_c a[c]^2 * invdeg[c]
    float2 f0 = __half22float2(c0), f1 = __half22float2(c1);
    float2 f2 = __half22float2(c2), f3 = __half22float2(c3);
    float af[8] = {f0.x, f0.y, f1.x, f1.y, f2.x, f2.y, f3.x, f3.y};
    int base = 8 * t;
    float4 iv0 = *reinterpret_cast<const float4*>(g_invdeg + base);
    float4 iv1 = *reinterpret_cast<const float4*>(g_invdeg + base + 4);
    float iv[8] = {iv0.x, iv0.y, iv0.z, iv0.w, iv1.x, iv1.y, iv1.z, iv1.w};
    float s6 = 0.f;
    #pragma unroll
    for (int k = 0; k < 8; k++) s6 = fmaf(af[k] * iv[k], af[k], s6);

    __shared__ float red[16];
    s6 = warp_red(s6);
    int wid = t >> 5, lane = t & 31;
    if (lane == 0) red[wid] = s6;
    __syncthreads();
    if (t == 0) {
        float x = 0.f;
        for (int q = 0; q < 16; q++) x += red[q];
        g_d6[i] = g_deg[i] * x * (1.0f / (FSCALE * FSCALE));
    }
}

// ------- K6: T4 row (fp8 gather, half2 acc) + d5, d7, d8 + projection -------
__global__ void __launch_bounds__(512) k_final(const float* __restrict__ W,
                                               const float* __restrict__ b,
                                               float* __restrict__ out) {
    int i = blockIdx.x, t = threadIdx.x;
    __shared__ int   scol[CAP];
    __shared__ float sw[CAP];
    int nn = g_nnz[i];
    if (t < nn) {
        int2 cw = g_cw[i * CAP + t];
        scol[t] = cw.x;
        sw[t]   = __int_as_float(cw.y);
    }
    __syncthreads();
    __half2 c0 = __half2half2(__ushort_as_half(0));
    __half2 c1 = c0, c2 = c0, c3 = c0;           // 256*T4[i, 8t..8t+7]
    for (int p = 0; p < nn; p++) {
        int j = scol[p];
        __half2 w2 = __float2half2_rn(sw[p]);
        uint2 v = __ldg(reinterpret_cast<const uint2*>(g_T3q + (size_t)j * NN) + t);
        c0 = __hfma2(fp8_to_h2((unsigned short)(v.x & 0xffffu)), w2, c0);
        c1 = __hfma2(fp8_to_h2((unsigned short)(v.x >> 16)),     w2, c1);
        c2 = __hfma2(fp8_to_h2((unsigned short)(v.y & 0xffffu)), w2, c2);
        c3 = __hfma2(fp8_to_h2((unsigned short)(v.y >> 16)),     w2, c3);
    }
    float2 f0 = __half22float2(c0), f1 = __half22float2(c1);
    float2 f2 = __half22float2(c2), f3 = __half22float2(c3);
    float af[8] = {f0.x, f0.y, f1.x, f1.y, f2.x, f2.y, f3.x, f3.y};

    // own T3 row (fp8, x256)
    uint2 ov = __ldg(reinterpret_cast<const uint2*>(g_T3q + (size_t)i * NN) + t);
    float2 o0 = __half22float2(fp8_to_h2((unsigned short)(ov.x & 0xffffu)));
    float2 o1 = __half22float2(fp8_to_h2((unsigned short)(ov.x >> 16)));
    float2 o2 = __half22float2(fp8_to_h2((unsigned short)(ov.y & 0xffffu)));
    float2 o3 = __half22float2(fp8_to_h2((unsigned short)(ov.y >> 16)));
    float t3o[8] = {o0.x, o0.y, o1.x, o1.y, o2.x, o2.y, o3.x, o3.y};

    int base = 8 * t;
    float4 iv0 = *reinterpret_cast<const float4*>(g_invdeg + base);
    float4 iv1 = *reinterpret_cast<const float4*>(g_invdeg + base + 4);
    float iv[8] = {iv0.x, iv0.y, iv0.z, iv0.w, iv1.x, iv1.y, iv1.z, iv1.w};
    float s7 = 0.f, s8 = 0.f;
    #pragma unroll
    for (int k = 0; k < 8; k++) {
        float wa = af[k] * iv[k];
        s7 = fmaf(t3o[k], wa, s7);
        s8 = fmaf(af[k],  wa, s8);
    }
    // d5 sparse (1,4) split: sum over neighbors p with col owned by this thread
    float s5 = 0.f;
    for (int p = 0; p < nn; p++) {
        int j = scol[p];
        if ((j >> 3) == t) s5 += sw[p] * af[j & 7] * iv[j & 7];
    }

    __shared__ float red[3][16];
    s5 = warp_red(s5); s7 = warp_red(s7); s8 = warp_red(s8);
    int wid = t >> 5, lane = t & 31;
    if (lane == 0) { red[0][wid] = s5; red[1][wid] = s7; red[2][wid] = s8; }
    __syncthreads();
    __shared__ float S[3];
    if (t < 3) {
        float x = 0.f;
        for (int q = 0; q < 16; q++) x += red[t][q];
        S[t] = x;
    }
    __syncthreads();

    if (t < DPE) {
        float deg = g_deg[i];
        float d1 = g_wii[i];
        float d2 = g_d2[i], d3 = g_d3[i], d4 = g_d4[i], d6 = g_d6[i];
        float d5 = deg * S[0] * (1.0f / FSCALE);
        float d7 = deg * S[1] * (1.0f / (FSCALE * FSCALE));
        float d8 = deg * S[2] * (1.0f / (FSCALE * FSCALE));
        float o = b[t];
        o = fmaf(d1, W[0 * DPE + t], o);
        o = fmaf(d2, W[1 * DPE + t], o);
        o = fmaf(d3, W[2 * DPE + t], o);
        o = fmaf(d4, W[3 * DPE + t], o);
        o = fmaf(d5, W[4 * DPE + t], o);
        o = fmaf(d6, W[5 * DPE + t], o);
        o = fmaf(d7, W[6 * DPE + t], o);
        o = fmaf(d8, W[7 * DPE + t], o);
        out[i * DPE + t] = o;
    }
}

extern "C" void kernel_launch(void* const* d_in, const int* in_sizes, int n_in,
                              void* d_out, int out_size) {
    const int*   edge = nullptr;
    const float* W    = nullptr;
    const float* bias = nullptr;
    for (int k = 0; k < n_in; k++) {
        if (in_sizes[k] == 2 * NE)       edge = (const int*)d_in[k];
        else if (in_sizes[k] == 8 * DPE) W    = (const float*)d_in[k];
        else if (in_sizes[k] == DPE)     bias = (const float*)d_in[k];
    }
    float* out = (float*)d_out;

    k_hinit  <<<(NN * CAP / 4) / 256, 256>>>();
    k_insert <<<(NE + 255) / 256, 256>>>(edge);
    k_compact<<<NN, 128>>>();
    k_t2     <<<NN, 512>>>();
    k_t3     <<<NN, 512>>>();
    k_final  <<<NN, 512>>>(W, bias, out);
}